// round 8
// baseline (speedup 1.0000x reference)
#include <cuda_runtime.h>
#include <cuda_bf16.h>
#include <cstdint>

// Problem constants
#define BB 4
#define N1 8192
#define N2 2048
#define INP 512
#define OUTP 256
#define M1 (BB * N1)   // 32768
#define M2 (BB * N2)   // 8192

// Device scratch
__device__ float g_y1[M1 * OUTP];     // x1@W1+b1  (32 MB)
__device__ float g_y2[M2 * OUTP];     // x2@W2+b2  (8 MB)
__device__ float g_Wt1[OUTP * OUTP];  // W1^T  [N,K]
__device__ float g_Wt2[OUTP * INP];   // W2^T  [N,K]
__device__ float g_stats1[2 * OUTP];
__device__ float g_stats2[2 * OUTP];
__device__ float g_ab1[2 * OUTP];
__device__ float g_ab2[2 * OUTP];
__device__ int   g_idx[BB * N1 * 3];
__device__ float g_w[BB * N1 * 3];

// ---------------------------------------------------------------------------
__device__ __forceinline__ uint32_t smem_u32(const void* p) {
    uint32_t a;
    asm("{ .reg .u64 t; cvta.to.shared.u64 t, %1; cvt.u32.u64 %0, t; }"
        : "=r"(a) : "l"(p));
    return a;
}

__device__ __forceinline__ void ldmx4(uint32_t addr, uint32_t* r) {
    asm volatile("ldmatrix.sync.aligned.m8n8.x4.shared.b16 {%0,%1,%2,%3}, [%4];"
                 : "=r"(r[0]), "=r"(r[1]), "=r"(r[2]), "=r"(r[3]) : "r"(addr));
}

__device__ __forceinline__ void mma16816(float* c, const uint32_t* a,
                                         const uint32_t* b) {
    asm volatile(
        "mma.sync.aligned.m16n8k16.row.col.f32.bf16.bf16.f32 "
        "{%0,%1,%2,%3}, {%4,%5,%6,%7}, {%8,%9}, {%0,%1,%2,%3};"
        : "+f"(c[0]), "+f"(c[1]), "+f"(c[2]), "+f"(c[3])
        : "r"(a[0]), "r"(a[1]), "r"(a[2]), "r"(a[3]), "r"(b[0]), "r"(b[1]));
}

// ---------------------------------------------------------------------------
__global__ void zero_stats_kernel() {
    int t = threadIdx.x;
    if (t < 2 * OUTP) { g_stats1[t] = 0.f; g_stats2[t] = 0.f; }
}

// Tiled transpose: dst[C][R] = src[R][C]^T. block (32,8), grid (C/32, R/32)
__global__ __launch_bounds__(256) void transpose_kernel(
    const float* __restrict__ src, float* __restrict__ dst, int R, int C)
{
    __shared__ float t[32][33];
    int bx = blockIdx.x * 32, by = blockIdx.y * 32;
    int x = bx + threadIdx.x;
    #pragma unroll
    for (int i = 0; i < 32; i += 8)
        t[threadIdx.y + i][threadIdx.x] = src[(size_t)(by + threadIdx.y + i) * C + x];
    __syncthreads();
    int x2 = by + threadIdx.x;
    #pragma unroll
    for (int i = 0; i < 32; i += 8)
        dst[(size_t)(bx + threadIdx.y + i) * R + x2] = t[threadIdx.x][threadIdx.y + i];
}

// ---------------------------------------------------------------------------
// Split-bf16 HMMA GEMM: C[M,256] = A[M,K] @ Wt[256,K]^T + bias
// CTA tile 128x128, BK=32, 512 threads / 16 warps as 4(m) x 4(n),
// warp tile 32x32. A,B split to bf16 hi/lo in smem; 3-term MMA, fp32 acc.
// Fused epilogue: per-channel sum/sumsq into stats.
#define ROWE 40            // smem row stride in bf16 elements (80 bytes)
#define ROWB 80

template<int K>
__global__ __launch_bounds__(512) void gemm_hmma_kernel(
    const float* __restrict__ A, const float* __restrict__ Wt,
    const float* __restrict__ bias, float* __restrict__ C,
    float* __restrict__ stats)
{
    __shared__ __nv_bfloat16 sAhi[128 * ROWE];
    __shared__ __nv_bfloat16 sAlo[128 * ROWE];
    __shared__ __nv_bfloat16 sBhi[128 * ROWE];
    __shared__ __nv_bfloat16 sBlo[128 * ROWE];

    const int tid = threadIdx.x;
    const int wid = tid >> 5;
    const int lane = tid & 31;
    const int gid = lane >> 2;   // mma group
    const int tig = lane & 3;

    const int rowBase = blockIdx.y * 128;
    const int colBase = blockIdx.x * 128;
    const int m0 = (wid & 3) * 32;      // 4 m-groups of 32 rows
    const int n0 = (wid >> 2) * 32;     // 4 n-groups of 32 cols

    const uint32_t uAhi = smem_u32(sAhi), uAlo = smem_u32(sAlo);
    const uint32_t uBhi = smem_u32(sBhi), uBlo = smem_u32(sBlo);

    // ldmatrix per-lane address components
    const int q = lane >> 3, ri = lane & 7;
    const uint32_t aOff = (uint32_t)(m0 + (q & 1) * 8 + ri) * ROWB + (q >> 1) * 16;
    const uint32_t bOff = (uint32_t)(n0 + (q >> 1) * 8 + ri) * ROWB + (q & 1) * 16;

    // Loader indices: i = tid + l*512; row = i>>3 (64/step), c4 = (i&7)*4
    const int ldRow = tid >> 3;
    const int ldC4  = (tid & 7) * 4;

    float acc[2][4][4];
    #pragma unroll
    for (int mt = 0; mt < 2; mt++)
        #pragma unroll
        for (int nt = 0; nt < 4; nt++)
            #pragma unroll
            for (int e = 0; e < 4; e++) acc[mt][nt][e] = 0.f;

    for (int k0 = 0; k0 < K; k0 += 32) {
        // ---- load + split-convert A tile (128 x 32 fp32) ----
        #pragma unroll
        for (int l = 0; l < 2; l++) {
            int r = ldRow + l * 64;
            float4 v = *(const float4*)(A + (size_t)(rowBase + r) * K + k0 + ldC4);
            __nv_bfloat16 h0 = __float2bfloat16_rn(v.x);
            __nv_bfloat16 h1 = __float2bfloat16_rn(v.y);
            __nv_bfloat16 h2 = __float2bfloat16_rn(v.z);
            __nv_bfloat16 h3 = __float2bfloat16_rn(v.w);
            __nv_bfloat16 l0 = __float2bfloat16_rn(v.x - __bfloat162float(h0));
            __nv_bfloat16 l1 = __float2bfloat16_rn(v.y - __bfloat162float(h1));
            __nv_bfloat16 l2 = __float2bfloat16_rn(v.z - __bfloat162float(h2));
            __nv_bfloat16 l3 = __float2bfloat16_rn(v.w - __bfloat162float(h3));
            __nv_bfloat162 hA(h0, h1), hB(h2, h3), lA(l0, l1), lB(l2, l3);
            int o = r * ROWE + ldC4;
            *(uint2*)&sAhi[o] = make_uint2(*(uint32_t*)&hA, *(uint32_t*)&hB);
            *(uint2*)&sAlo[o] = make_uint2(*(uint32_t*)&lA, *(uint32_t*)&lB);
        }
        // ---- load + split-convert B tile (128 x 32 fp32 of Wt) ----
        #pragma unroll
        for (int l = 0; l < 2; l++) {
            int r = ldRow + l * 64;
            float4 v = *(const float4*)(Wt + (size_t)(colBase + r) * K + k0 + ldC4);
            __nv_bfloat16 h0 = __float2bfloat16_rn(v.x);
            __nv_bfloat16 h1 = __float2bfloat16_rn(v.y);
            __nv_bfloat16 h2 = __float2bfloat16_rn(v.z);
            __nv_bfloat16 h3 = __float2bfloat16_rn(v.w);
            __nv_bfloat16 l0 = __float2bfloat16_rn(v.x - __bfloat162float(h0));
            __nv_bfloat16 l1 = __float2bfloat16_rn(v.y - __bfloat162float(h1));
            __nv_bfloat16 l2 = __float2bfloat16_rn(v.z - __bfloat162float(h2));
            __nv_bfloat16 l3 = __float2bfloat16_rn(v.w - __bfloat162float(h3));
            __nv_bfloat162 hA(h0, h1), hB(h2, h3), lA(l0, l1), lB(l2, l3);
            int o = r * ROWE + ldC4;
            *(uint2*)&sBhi[o] = make_uint2(*(uint32_t*)&hA, *(uint32_t*)&hB);
            *(uint2*)&sBlo[o] = make_uint2(*(uint32_t*)&lA, *(uint32_t*)&lB);
        }
        __syncthreads();

        // ---- MMA: 2 k16 steps, 2 m-tiles x 4 n-tiles, 3 split terms ----
        #pragma unroll
        for (int kk = 0; kk < 2; kk++) {
            uint32_t bh[4][2], bl[4][2];
            #pragma unroll
            for (int p = 0; p < 2; p++) {
                uint32_t r4[4];
                ldmx4(uBhi + bOff + p * 16 * ROWB + kk * 32, r4);
                bh[2 * p][0] = r4[0]; bh[2 * p][1] = r4[1];
                bh[2 * p + 1][0] = r4[2]; bh[2 * p + 1][1] = r4[3];
                ldmx4(uBlo + bOff + p * 16 * ROWB + kk * 32, r4);
                bl[2 * p][0] = r4[0]; bl[2 * p][1] = r4[1];
                bl[2 * p + 1][0] = r4[2]; bl[2 * p + 1][1] = r4[3];
            }
            #pragma unroll
            for (int mt = 0; mt < 2; mt++) {
                uint32_t ah[4], al[4];
                ldmx4(uAhi + aOff + mt * 16 * ROWB + kk * 32, ah);
                ldmx4(uAlo + aOff + mt * 16 * ROWB + kk * 32, al);
                #pragma unroll
                for (int nt = 0; nt < 4; nt++) {
                    mma16816(acc[mt][nt], ah, bh[nt]);
                    mma16816(acc[mt][nt], ah, bl[nt]);
                    mma16816(acc[mt][nt], al, bh[nt]);
                }
            }
        }
        __syncthreads();
    }

    // ---- epilogue: acc + bias -> C, fused per-channel stats ----
    float* sred = (float*)sAhi;   // [0..127]=sum, [128..255]=sumsq
    if (tid < 256) sred[tid] = 0.f;
    __syncthreads();

    #pragma unroll
    for (int nt = 0; nt < 4; nt++) {
        const int lc = n0 + nt * 8 + tig * 2;     // 0..126
        const int cg = colBase + lc;
        float2 bv = *(const float2*)(bias + cg);
        float s0 = 0.f, s1 = 0.f, q0 = 0.f, q1 = 0.f;
        #pragma unroll
        for (int mt = 0; mt < 2; mt++) {
            int rg0 = rowBase + m0 + mt * 16 + gid;
            float vx = acc[mt][nt][0] + bv.x;
            float vy = acc[mt][nt][1] + bv.y;
            float wx = acc[mt][nt][2] + bv.x;
            float wy = acc[mt][nt][3] + bv.y;
            *(float2*)(C + (size_t)rg0 * OUTP + cg) = make_float2(vx, vy);
            *(float2*)(C + (size_t)(rg0 + 8) * OUTP + cg) = make_float2(wx, wy);
            s0 += vx + wx;
            s1 += vy + wy;
            q0 += vx * vx + wx * wx;
            q1 += vy * vy + wy * wy;
        }
        atomicAdd(&sred[lc], s0);
        atomicAdd(&sred[lc + 1], s1);
        atomicAdd(&sred[128 + lc], q0);
        atomicAdd(&sred[128 + lc + 1], q1);
    }
    __syncthreads();
    if (tid < 128) {
        atomicAdd(&stats[colBase + tid], sred[tid]);
        atomicAdd(&stats[OUTP + colBase + tid], sred[128 + tid]);
    }
}

// ---------------------------------------------------------------------------
__global__ void finalize_kernel(const float* __restrict__ stats,
                                const float* __restrict__ gamma,
                                const float* __restrict__ beta,
                                float inv_count, float* __restrict__ ab)
{
    int c = threadIdx.x;
    float mean = stats[c] * inv_count;
    float var  = stats[OUTP + c] * inv_count - mean * mean;
    float scale = gamma[c] * rsqrtf(var + 1e-5f);
    ab[c]        = scale;
    ab[OUTP + c] = beta[c] - mean * scale;
}

// ---------------------------------------------------------------------------
// 3-NN, ILP-2 (two candidate streams, merged; strict < keeps first-occurrence
// tie rule since stream-B indices are always larger).
__global__ __launch_bounds__(256) void knn_kernel(
    const float* __restrict__ p1, const float* __restrict__ p2)
{
    __shared__ float4 sp[N2];
    const int b     = blockIdx.x >> 5;
    const int chunk = blockIdx.x & 31;

    const float* P2 = p2 + (size_t)b * N2 * 3;
    for (int i = threadIdx.x; i < N2; i += 256) {
        float x = P2[i * 3 + 0], y = P2[i * 3 + 1], z = P2[i * 3 + 2];
        sp[i] = make_float4(x, y, z, fmaf(x, x, fmaf(y, y, z * z)));
    }
    __syncthreads();

    const int n = chunk * 256 + threadIdx.x;
    const float* P1 = p1 + ((size_t)b * N1 + n) * 3;
    const float px = P1[0], py = P1[1], pz = P1[2];
    const float s1 = fmaf(px, px, fmaf(py, py, pz * pz));

    float a0 = 1e30f, a1 = 1e30f, a2 = 1e30f;
    int   ja0 = 0,    ja1 = 0,    ja2 = 0;
    float c0 = 1e30f, c1 = 1e30f, c2 = 1e30f;
    int   jc0 = 0,    jc1 = 0,    jc2 = 0;

    #pragma unroll 2
    for (int j = 0; j < N2 / 2; j++) {
        float4 qa = sp[j];
        float4 qb = sp[j + N2 / 2];
        float dotA = fmaf(px, qa.x, fmaf(py, qa.y, pz * qa.z));
        float dotB = fmaf(px, qb.x, fmaf(py, qb.y, pz * qb.z));
        float dA = (s1 + qa.w) - 2.f * dotA;
        float dB = (s1 + qb.w) - 2.f * dotB;
        if (dA < a2) {
            if (dA < a1) {
                a2 = a1; ja2 = ja1;
                if (dA < a0) { a1 = a0; ja1 = ja0; a0 = dA; ja0 = j; }
                else         { a1 = dA; ja1 = j; }
            } else { a2 = dA; ja2 = j; }
        }
        if (dB < c2) {
            if (dB < c1) {
                c2 = c1; jc2 = jc1;
                if (dB < c0) { c1 = c0; jc1 = jc0; c0 = dB; jc0 = j + N2 / 2; }
                else         { c1 = dB; jc1 = j + N2 / 2; }
            } else { c2 = dB; jc2 = j + N2 / 2; }
        }
    }

    #pragma unroll
    for (int t = 0; t < 3; t++) {
        float d = (t == 0) ? c0 : (t == 1) ? c1 : c2;
        int   jj = (t == 0) ? jc0 : (t == 1) ? jc1 : jc2;
        if (d < a2) {
            if (d < a1) {
                a2 = a1; ja2 = ja1;
                if (d < a0) { a1 = a0; ja1 = ja0; a0 = d; ja0 = jj; }
                else        { a1 = d;  ja1 = jj; }
            } else { a2 = d; ja2 = jj; }
        }
    }

    float r0 = 1.f / (a0 + 1e-8f);
    float r1 = 1.f / (a1 + 1e-8f);
    float r2 = 1.f / (a2 + 1e-8f);
    float rs = 1.f / (r0 + r1 + r2);

    size_t o = ((size_t)b * N1 + n) * 3;
    g_idx[o + 0] = b * N2 + ja0;
    g_idx[o + 1] = b * N2 + ja1;
    g_idx[o + 2] = b * N2 + ja2;
    g_w[o + 0] = r0 * rs;
    g_w[o + 1] = r1 * rs;
    g_w[o + 2] = r2 * rs;
}

// ---------------------------------------------------------------------------
__global__ __launch_bounds__(256) void out_kernel(float* __restrict__ out)
{
    const int r = blockIdx.x;
    const int c = threadIdx.x;

    const float a1 = g_ab1[c], s1 = g_ab1[OUTP + c];
    const float a2 = g_ab2[c], s2 = g_ab2[OUTP + c];

    const size_t o3 = (size_t)r * 3;
    const int   j0 = g_idx[o3 + 0], j1 = g_idx[o3 + 1], j2 = g_idx[o3 + 2];
    const float w0 = g_w[o3 + 0],   w1 = g_w[o3 + 1],   w2 = g_w[o3 + 2];

    float v1 = fmaxf(fmaf(g_y1[(size_t)r * OUTP + c], a1, s1), 0.f);
    float h0 = fmaxf(fmaf(g_y2[(size_t)j0 * OUTP + c], a2, s2), 0.f);
    float h1 = fmaxf(fmaf(g_y2[(size_t)j1 * OUTP + c], a2, s2), 0.f);
    float h2 = fmaxf(fmaf(g_y2[(size_t)j2 * OUTP + c], a2, s2), 0.f);

    out[(size_t)r * OUTP + c] = v1 + fmaf(w0, h0, fmaf(w1, h1, w2 * h2));
}

// ---------------------------------------------------------------------------
extern "C" void kernel_launch(void* const* d_in, const int* in_sizes, int n_in,
                              void* d_out, int out_size)
{
    const float* p1     = (const float*)d_in[0];
    const float* x1     = (const float*)d_in[1];
    const float* p2     = (const float*)d_in[2];
    const float* x2     = (const float*)d_in[3];
    const float* W1     = (const float*)d_in[4];
    const float* b1     = (const float*)d_in[5];
    const float* gamma1 = (const float*)d_in[6];
    const float* beta1  = (const float*)d_in[7];
    const float* W2     = (const float*)d_in[8];
    const float* b2     = (const float*)d_in[9];
    const float* gamma2 = (const float*)d_in[10];
    const float* beta2  = (const float*)d_in[11];
    float* out = (float*)d_out;

    float *y1, *y2, *st1, *st2, *ab1, *ab2, *wt1, *wt2;
    cudaGetSymbolAddress((void**)&y1,  g_y1);
    cudaGetSymbolAddress((void**)&y2,  g_y2);
    cudaGetSymbolAddress((void**)&st1, g_stats1);
    cudaGetSymbolAddress((void**)&st2, g_stats2);
    cudaGetSymbolAddress((void**)&ab1, g_ab1);
    cudaGetSymbolAddress((void**)&ab2, g_ab2);
    cudaGetSymbolAddress((void**)&wt1, g_Wt1);
    cudaGetSymbolAddress((void**)&wt2, g_Wt2);

    zero_stats_kernel<<<1, 512>>>();

    // Transpose weights into [N,K]
    transpose_kernel<<<dim3(OUTP / 32, INP / 32), dim3(32, 8)>>>(W2, wt2, INP, OUTP);
    transpose_kernel<<<dim3(OUTP / 32, OUTP / 32), dim3(32, 8)>>>(W1, wt1, OUTP, OUTP);

    // Split-bf16 HMMA GEMMs, 512 threads / 16 warps, fused stats
    gemm_hmma_kernel<INP><<<dim3(2, M2 / 128), 512>>>(x2, wt2, b2, y2, st2);
    gemm_hmma_kernel<OUTP><<<dim3(2, M1 / 128), 512>>>(x1, wt1, b1, y1, st1);

    finalize_kernel<<<1, 256>>>(st2, gamma2, beta2, 1.f / (float)M2, ab2);
    finalize_kernel<<<1, 256>>>(st1, gamma1, beta1, 1.f / (float)M1, ab1);

    knn_kernel<<<BB * (N1 / 256), 256>>>(p1, p2);

    out_kernel<<<M1, 256>>>(out);
}

// round 9
// speedup vs baseline: 1.1918x; 1.1918x over previous
#include <cuda_runtime.h>
#include <cuda_bf16.h>
#include <cstdint>

// Problem constants
#define BB 4
#define N1 8192
#define N2 2048
#define INP 512
#define OUTP 256
#define M1 (BB * N1)   // 32768
#define M2 (BB * N2)   // 8192

// Device scratch
__device__ float g_y1[M1 * OUTP];     // x1@W1+b1  (32 MB)
__device__ float g_y2[M2 * OUTP];     // x2@W2+b2  (8 MB)
__device__ float g_Wt1[OUTP * OUTP];  // W1^T  [N,K]
__device__ float g_Wt2[OUTP * INP];   // W2^T  [N,K]
__device__ float g_stats1[2 * OUTP];
__device__ float g_stats2[2 * OUTP];
__device__ float g_ab1[2 * OUTP];
__device__ float g_ab2[2 * OUTP];
__device__ int   g_idx[BB * N1 * 3];
__device__ float g_w[BB * N1 * 3];

// ---------------------------------------------------------------------------
__device__ __forceinline__ uint32_t smem_u32(const void* p) {
    uint32_t a;
    asm("{ .reg .u64 t; cvta.to.shared.u64 t, %1; cvt.u32.u64 %0, t; }"
        : "=r"(a) : "l"(p));
    return a;
}

__device__ __forceinline__ void ldmx4(uint32_t addr, uint32_t* r) {
    asm volatile("ldmatrix.sync.aligned.m8n8.x4.shared.b16 {%0,%1,%2,%3}, [%4];"
                 : "=r"(r[0]), "=r"(r[1]), "=r"(r[2]), "=r"(r[3]) : "r"(addr));
}

__device__ __forceinline__ void mma16816(float* c, const uint32_t* a,
                                         const uint32_t* b) {
    asm volatile(
        "mma.sync.aligned.m16n8k16.row.col.f32.bf16.bf16.f32 "
        "{%0,%1,%2,%3}, {%4,%5,%6,%7}, {%8,%9}, {%0,%1,%2,%3};"
        : "+f"(c[0]), "+f"(c[1]), "+f"(c[2]), "+f"(c[3])
        : "r"(a[0]), "r"(a[1]), "r"(a[2]), "r"(a[3]), "r"(b[0]), "r"(b[1]));
}

// ---------------------------------------------------------------------------
__global__ void zero_stats_kernel() {
    int t = threadIdx.x;
    if (t < 2 * OUTP) { g_stats1[t] = 0.f; g_stats2[t] = 0.f; }
}

// Tiled transpose: dst[C][R] = src[R][C]^T. block (32,8), grid (C/32, R/32)
__global__ __launch_bounds__(256) void transpose_kernel(
    const float* __restrict__ src, float* __restrict__ dst, int R, int C)
{
    __shared__ float t[32][33];
    int bx = blockIdx.x * 32, by = blockIdx.y * 32;
    int x = bx + threadIdx.x;
    #pragma unroll
    for (int i = 0; i < 32; i += 8)
        t[threadIdx.y + i][threadIdx.x] = src[(size_t)(by + threadIdx.y + i) * C + x];
    __syncthreads();
    int x2 = by + threadIdx.x;
    #pragma unroll
    for (int i = 0; i < 32; i += 8)
        dst[(size_t)(bx + threadIdx.y + i) * R + x2] = t[threadIdx.x][threadIdx.y + i];
}

// ---------------------------------------------------------------------------
// Split-bf16 HMMA GEMM (R3 champion config): C[M,256] = A[M,K] @ Wt[256,K]^T + bias
// CTA tile 128x128, BK=32, 8 warps (warp tile 64x32).
// A,B split into bf16 hi/lo in smem; 3-term MMA (hh + hl + lh), fp32 acc.
#define ROWE 40            // smem row stride in bf16 elements (80 bytes)
#define ROWB 80

template<int K>
__global__ __launch_bounds__(256) void gemm_hmma_kernel(
    const float* __restrict__ A, const float* __restrict__ Wt,
    const float* __restrict__ bias, float* __restrict__ C)
{
    __shared__ __nv_bfloat16 sAhi[128 * ROWE];
    __shared__ __nv_bfloat16 sAlo[128 * ROWE];
    __shared__ __nv_bfloat16 sBhi[128 * ROWE];
    __shared__ __nv_bfloat16 sBlo[128 * ROWE];

    const int tid = threadIdx.x;
    const int wid = tid >> 5;
    const int lane = tid & 31;
    const int gid = lane >> 2;   // mma group
    const int tig = lane & 3;

    const int rowBase = blockIdx.y * 128;
    const int colBase = blockIdx.x * 128;
    const int m0 = (wid & 1) * 64;
    const int n0 = (wid >> 1) * 32;

    const uint32_t uAhi = smem_u32(sAhi), uAlo = smem_u32(sAlo);
    const uint32_t uBhi = smem_u32(sBhi), uBlo = smem_u32(sBlo);

    // ldmatrix per-lane address components
    const int q = lane >> 3, ri = lane & 7;
    const uint32_t aOff = (uint32_t)(m0 + (q & 1) * 8 + ri) * ROWB + (q >> 1) * 16;
    const uint32_t bOff = (uint32_t)(n0 + (q >> 1) * 8 + ri) * ROWB + (q & 1) * 16;

    // Loader indices: i = tid + l*256; row = i>>3, c4 = (i&7)*4
    const int ldRow = tid >> 3;
    const int ldC4  = (tid & 7) * 4;

    float acc[4][4][4];
    #pragma unroll
    for (int mt = 0; mt < 4; mt++)
        #pragma unroll
        for (int nt = 0; nt < 4; nt++)
            #pragma unroll
            for (int e = 0; e < 4; e++) acc[mt][nt][e] = 0.f;

    for (int k0 = 0; k0 < K; k0 += 32) {
        // ---- load + split-convert A tile (128 x 32 fp32) ----
        #pragma unroll
        for (int l = 0; l < 4; l++) {
            int r = ldRow + l * 32;
            float4 v = *(const float4*)(A + (size_t)(rowBase + r) * K + k0 + ldC4);
            __nv_bfloat16 h0 = __float2bfloat16_rn(v.x);
            __nv_bfloat16 h1 = __float2bfloat16_rn(v.y);
            __nv_bfloat16 h2 = __float2bfloat16_rn(v.z);
            __nv_bfloat16 h3 = __float2bfloat16_rn(v.w);
            __nv_bfloat16 l0 = __float2bfloat16_rn(v.x - __bfloat162float(h0));
            __nv_bfloat16 l1 = __float2bfloat16_rn(v.y - __bfloat162float(h1));
            __nv_bfloat16 l2 = __float2bfloat16_rn(v.z - __bfloat162float(h2));
            __nv_bfloat16 l3 = __float2bfloat16_rn(v.w - __bfloat162float(h3));
            __nv_bfloat162 hA(h0, h1), hB(h2, h3), lA(l0, l1), lB(l2, l3);
            int o = r * ROWE + ldC4;
            *(uint2*)&sAhi[o] = make_uint2(*(uint32_t*)&hA, *(uint32_t*)&hB);
            *(uint2*)&sAlo[o] = make_uint2(*(uint32_t*)&lA, *(uint32_t*)&lB);
        }
        // ---- load + split-convert B tile (128 x 32 fp32 of Wt) ----
        #pragma unroll
        for (int l = 0; l < 4; l++) {
            int r = ldRow + l * 32;
            float4 v = *(const float4*)(Wt + (size_t)(colBase + r) * K + k0 + ldC4);
            __nv_bfloat16 h0 = __float2bfloat16_rn(v.x);
            __nv_bfloat16 h1 = __float2bfloat16_rn(v.y);
            __nv_bfloat16 h2 = __float2bfloat16_rn(v.z);
            __nv_bfloat16 h3 = __float2bfloat16_rn(v.w);
            __nv_bfloat16 l0 = __float2bfloat16_rn(v.x - __bfloat162float(h0));
            __nv_bfloat16 l1 = __float2bfloat16_rn(v.y - __bfloat162float(h1));
            __nv_bfloat16 l2 = __float2bfloat16_rn(v.z - __bfloat162float(h2));
            __nv_bfloat16 l3 = __float2bfloat16_rn(v.w - __bfloat162float(h3));
            __nv_bfloat162 hA(h0, h1), hB(h2, h3), lA(l0, l1), lB(l2, l3);
            int o = r * ROWE + ldC4;
            *(uint2*)&sBhi[o] = make_uint2(*(uint32_t*)&hA, *(uint32_t*)&hB);
            *(uint2*)&sBlo[o] = make_uint2(*(uint32_t*)&lA, *(uint32_t*)&lB);
        }
        __syncthreads();

        // ---- MMA: 2 k16 steps, 4 m-tiles x 4 n-tiles, 3 split terms ----
        #pragma unroll
        for (int kk = 0; kk < 2; kk++) {
            uint32_t bh[4][2], bl[4][2];
            #pragma unroll
            for (int p = 0; p < 2; p++) {
                uint32_t r4[4];
                ldmx4(uBhi + bOff + p * 16 * ROWB + kk * 32, r4);
                bh[2 * p][0] = r4[0]; bh[2 * p][1] = r4[1];
                bh[2 * p + 1][0] = r4[2]; bh[2 * p + 1][1] = r4[3];
                ldmx4(uBlo + bOff + p * 16 * ROWB + kk * 32, r4);
                bl[2 * p][0] = r4[0]; bl[2 * p][1] = r4[1];
                bl[2 * p + 1][0] = r4[2]; bl[2 * p + 1][1] = r4[3];
            }
            #pragma unroll
            for (int mt = 0; mt < 4; mt++) {
                uint32_t ah[4], al[4];
                ldmx4(uAhi + aOff + mt * 16 * ROWB + kk * 32, ah);
                ldmx4(uAlo + aOff + mt * 16 * ROWB + kk * 32, al);
                #pragma unroll
                for (int nt = 0; nt < 4; nt++) {
                    mma16816(acc[mt][nt], ah, bh[nt]);
                    mma16816(acc[mt][nt], ah, bl[nt]);
                    mma16816(acc[mt][nt], al, bh[nt]);
                }
            }
        }
        __syncthreads();
    }

    // ---- epilogue: acc + bias -> C ----
    #pragma unroll
    for (int nt = 0; nt < 4; nt++) {
        const int cg = colBase + n0 + nt * 8 + tig * 2;
        float2 bv = *(const float2*)(bias + cg);
        #pragma unroll
        for (int mt = 0; mt < 4; mt++) {
            int rg0 = rowBase + m0 + mt * 16 + gid;
            float2 v0 = make_float2(acc[mt][nt][0] + bv.x, acc[mt][nt][1] + bv.y);
            float2 v1 = make_float2(acc[mt][nt][2] + bv.x, acc[mt][nt][3] + bv.y);
            *(float2*)(C + (size_t)rg0 * OUTP + cg) = v0;
            *(float2*)(C + (size_t)(rg0 + 8) * OUTP + cg) = v1;
        }
    }
}

// ---------------------------------------------------------------------------
__global__ __launch_bounds__(256) void stats_kernel(
    const float* __restrict__ y, int rows, float* __restrict__ stats)
{
    int c = threadIdx.x;
    float s = 0.f, q = 0.f;
    for (int r = blockIdx.x; r < rows; r += gridDim.x) {
        float v = y[(size_t)r * OUTP + c];
        s += v;
        q = fmaf(v, v, q);
    }
    atomicAdd(&stats[c], s);
    atomicAdd(&stats[OUTP + c], q);
}

__global__ void finalize_kernel(const float* __restrict__ stats,
                                const float* __restrict__ gamma,
                                const float* __restrict__ beta,
                                float inv_count, float* __restrict__ ab)
{
    int c = threadIdx.x;
    float mean = stats[c] * inv_count;
    float var  = stats[OUTP + c] * inv_count - mean * mean;
    float scale = gamma[c] * rsqrtf(var + 1e-5f);
    ab[c]        = scale;
    ab[OUTP + c] = beta[c] - mean * scale;
}

// ---------------------------------------------------------------------------
// 3-NN, ILP-2: two independent candidate streams, merged at the end.
// Strict < merge preserves the reference's first-occurrence tie rule since
// stream-B indices are always larger.
__global__ __launch_bounds__(256) void knn_kernel(
    const float* __restrict__ p1, const float* __restrict__ p2)
{
    __shared__ float4 sp[N2];
    const int b     = blockIdx.x >> 5;
    const int chunk = blockIdx.x & 31;

    const float* P2 = p2 + (size_t)b * N2 * 3;
    for (int i = threadIdx.x; i < N2; i += 256) {
        float x = P2[i * 3 + 0], y = P2[i * 3 + 1], z = P2[i * 3 + 2];
        sp[i] = make_float4(x, y, z, fmaf(x, x, fmaf(y, y, z * z)));
    }
    __syncthreads();

    const int n = chunk * 256 + threadIdx.x;
    const float* P1 = p1 + ((size_t)b * N1 + n) * 3;
    const float px = P1[0], py = P1[1], pz = P1[2];
    const float s1 = fmaf(px, px, fmaf(py, py, pz * pz));

    float a0 = 1e30f, a1 = 1e30f, a2 = 1e30f;
    int   ja0 = 0,    ja1 = 0,    ja2 = 0;
    float c0 = 1e30f, c1 = 1e30f, c2 = 1e30f;
    int   jc0 = 0,    jc1 = 0,    jc2 = 0;

    #pragma unroll 2
    for (int j = 0; j < N2 / 2; j++) {
        float4 qa = sp[j];
        float4 qb = sp[j + N2 / 2];
        float dotA = fmaf(px, qa.x, fmaf(py, qa.y, pz * qa.z));
        float dotB = fmaf(px, qb.x, fmaf(py, qb.y, pz * qb.z));
        float dA = (s1 + qa.w) - 2.f * dotA;
        float dB = (s1 + qb.w) - 2.f * dotB;
        if (dA < a2) {
            if (dA < a1) {
                a2 = a1; ja2 = ja1;
                if (dA < a0) { a1 = a0; ja1 = ja0; a0 = dA; ja0 = j; }
                else         { a1 = dA; ja1 = j; }
            } else { a2 = dA; ja2 = j; }
        }
        if (dB < c2) {
            if (dB < c1) {
                c2 = c1; jc2 = jc1;
                if (dB < c0) { c1 = c0; jc1 = jc0; c0 = dB; jc0 = j + N2 / 2; }
                else         { c1 = dB; jc1 = j + N2 / 2; }
            } else { c2 = dB; jc2 = j + N2 / 2; }
        }
    }

    #pragma unroll
    for (int t = 0; t < 3; t++) {
        float d = (t == 0) ? c0 : (t == 1) ? c1 : c2;
        int   jj = (t == 0) ? jc0 : (t == 1) ? jc1 : jc2;
        if (d < a2) {
            if (d < a1) {
                a2 = a1; ja2 = ja1;
                if (d < a0) { a1 = a0; ja1 = ja0; a0 = d; ja0 = jj; }
                else        { a1 = d;  ja1 = jj; }
            } else { a2 = d; ja2 = jj; }
        }
    }

    float r0 = 1.f / (a0 + 1e-8f);
    float r1 = 1.f / (a1 + 1e-8f);
    float r2 = 1.f / (a2 + 1e-8f);
    float rs = 1.f / (r0 + r1 + r2);

    size_t o = ((size_t)b * N1 + n) * 3;
    g_idx[o + 0] = b * N2 + ja0;
    g_idx[o + 1] = b * N2 + ja1;
    g_idx[o + 2] = b * N2 + ja2;
    g_w[o + 0] = r0 * rs;
    g_w[o + 1] = r1 * rs;
    g_w[o + 2] = r2 * rs;
}

// ---------------------------------------------------------------------------
__global__ __launch_bounds__(256) void out_kernel(float* __restrict__ out)
{
    const int r = blockIdx.x;
    const int c = threadIdx.x;

    const float a1 = g_ab1[c], s1 = g_ab1[OUTP + c];
    const float a2 = g_ab2[c], s2 = g_ab2[OUTP + c];

    const size_t o3 = (size_t)r * 3;
    const int   j0 = g_idx[o3 + 0], j1 = g_idx[o3 + 1], j2 = g_idx[o3 + 2];
    const float w0 = g_w[o3 + 0],   w1 = g_w[o3 + 1],   w2 = g_w[o3 + 2];

    float v1 = fmaxf(fmaf(g_y1[(size_t)r * OUTP + c], a1, s1), 0.f);
    float h0 = fmaxf(fmaf(g_y2[(size_t)j0 * OUTP + c], a2, s2), 0.f);
    float h1 = fmaxf(fmaf(g_y2[(size_t)j1 * OUTP + c], a2, s2), 0.f);
    float h2 = fmaxf(fmaf(g_y2[(size_t)j2 * OUTP + c], a2, s2), 0.f);

    out[(size_t)r * OUTP + c] = v1 + fmaf(w0, h0, fmaf(w1, h1, w2 * h2));
}

// ---------------------------------------------------------------------------
extern "C" void kernel_launch(void* const* d_in, const int* in_sizes, int n_in,
                              void* d_out, int out_size)
{
    const float* p1     = (const float*)d_in[0];
    const float* x1     = (const float*)d_in[1];
    const float* p2     = (const float*)d_in[2];
    const float* x2     = (const float*)d_in[3];
    const float* W1     = (const float*)d_in[4];
    const float* b1     = (const float*)d_in[5];
    const float* gamma1 = (const float*)d_in[6];
    const float* beta1  = (const float*)d_in[7];
    const float* W2     = (const float*)d_in[8];
    const float* b2     = (const float*)d_in[9];
    const float* gamma2 = (const float*)d_in[10];
    const float* beta2  = (const float*)d_in[11];
    float* out = (float*)d_out;

    float *y1, *y2, *st1, *st2, *ab1, *ab2, *wt1, *wt2;
    cudaGetSymbolAddress((void**)&y1,  g_y1);
    cudaGetSymbolAddress((void**)&y2,  g_y2);
    cudaGetSymbolAddress((void**)&st1, g_stats1);
    cudaGetSymbolAddress((void**)&st2, g_stats2);
    cudaGetSymbolAddress((void**)&ab1, g_ab1);
    cudaGetSymbolAddress((void**)&ab2, g_ab2);
    cudaGetSymbolAddress((void**)&wt1, g_Wt1);
    cudaGetSymbolAddress((void**)&wt2, g_Wt2);

    zero_stats_kernel<<<1, 512>>>();

    // Transpose weights into [N,K]
    transpose_kernel<<<dim3(OUTP / 32, INP / 32), dim3(32, 8)>>>(W2, wt2, INP, OUTP);
    transpose_kernel<<<dim3(OUTP / 32, OUTP / 32), dim3(32, 8)>>>(W1, wt1, OUTP, OUTP);

    // Split-bf16 HMMA GEMMs (R3 champion config)
    gemm_hmma_kernel<INP><<<dim3(2, M2 / 128), 256>>>(x2, wt2, b2, y2);
    gemm_hmma_kernel<OUTP><<<dim3(2, M1 / 128), 256>>>(x1, wt1, b1, y1);

    stats_kernel<<<512, 256>>>(y2, M2, st2);
    stats_kernel<<<2048, 256>>>(y1, M1, st1);

    finalize_kernel<<<1, 256>>>(st2, gamma2, beta2, 1.f / (float)M2, ab2);
    finalize_kernel<<<1, 256>>>(st1, gamma1, beta1, 1.f / (float)M1, ab1);

    knn_kernel<<<BB * (N1 / 256), 256>>>(p1, p2);

    out_kernel<<<M1, 256>>>(out);
}

// round 10
// speedup vs baseline: 1.2027x; 1.0091x over previous
#include <cuda_runtime.h>
#include <cuda_bf16.h>
#include <cstdint>

// Problem constants
#define BB 4
#define N1 8192
#define N2 2048
#define INP 512
#define OUTP 256
#define M1 (BB * N1)   // 32768
#define M2 (BB * N2)   // 8192

// Device scratch
__device__ float g_y1[M1 * OUTP];     // x1@W1+b1  (32 MB)
__device__ float g_y2[M2 * OUTP];     // x2@W2+b2  (8 MB)
__device__ float g_Wt1[OUTP * OUTP];  // W1^T  [N,K]
__device__ float g_Wt2[OUTP * INP];   // W2^T  [N,K]
__device__ float g_stats1[2 * OUTP];
__device__ float g_stats2[2 * OUTP];
__device__ float g_ab1[2 * OUTP];
__device__ float g_ab2[2 * OUTP];
__device__ int   g_idx[BB * N1 * 3];
__device__ float g_w[BB * N1 * 3];

#define ROWE 40            // smem row stride in bf16 elements (80 bytes)
#define ROWB 80
#define GEMM2_CTAS 128     // (2 col blocks) x (64 row blocks)
#define GEMM1_CTAS 512     // (2 col blocks) x (256 row blocks)
#define KNN_CTAS   128

// ---------------------------------------------------------------------------
__device__ __forceinline__ uint32_t smem_u32(const void* p) {
    uint32_t a;
    asm("{ .reg .u64 t; cvta.to.shared.u64 t, %1; cvt.u32.u64 %0, t; }"
        : "=r"(a) : "l"(p));
    return a;
}

__device__ __forceinline__ void ldmx4(uint32_t addr, uint32_t* r) {
    asm volatile("ldmatrix.sync.aligned.m8n8.x4.shared.b16 {%0,%1,%2,%3}, [%4];"
                 : "=r"(r[0]), "=r"(r[1]), "=r"(r[2]), "=r"(r[3]) : "r"(addr));
}

__device__ __forceinline__ void mma16816(float* c, const uint32_t* a,
                                         const uint32_t* b) {
    asm volatile(
        "mma.sync.aligned.m16n8k16.row.col.f32.bf16.bf16.f32 "
        "{%0,%1,%2,%3}, {%4,%5,%6,%7}, {%8,%9}, {%0,%1,%2,%3};"
        : "+f"(c[0]), "+f"(c[1]), "+f"(c[2]), "+f"(c[3])
        : "r"(a[0]), "r"(a[1]), "r"(a[2]), "r"(a[3]), "r"(b[0]), "r"(b[1]));
}

// ---------------------------------------------------------------------------
__global__ void zero_stats_kernel() {
    int t = threadIdx.x;
    if (t < 2 * OUTP) { g_stats1[t] = 0.f; g_stats2[t] = 0.f; }
}

// Tiled transpose: dst[C][R] = src[R][C]^T. block (32,8), grid (C/32, R/32)
__global__ __launch_bounds__(256) void transpose_kernel(
    const float* __restrict__ src, float* __restrict__ dst, int R, int C)
{
    __shared__ float t[32][33];
    int bx = blockIdx.x * 32, by = blockIdx.y * 32;
    int x = bx + threadIdx.x;
    #pragma unroll
    for (int i = 0; i < 32; i += 8)
        t[threadIdx.y + i][threadIdx.x] = src[(size_t)(by + threadIdx.y + i) * C + x];
    __syncthreads();
    int x2 = by + threadIdx.x;
    #pragma unroll
    for (int i = 0; i < 32; i += 8)
        dst[(size_t)(bx + threadIdx.y + i) * R + x2] = t[threadIdx.x][threadIdx.y + i];
}

// ---------------------------------------------------------------------------
// GEMM body (R3 champion config, runtime K): C[128,128 tile] += A@Wt^T + bias
__device__ __forceinline__ void gemm_body(
    char* sm, const float* __restrict__ A, const float* __restrict__ Wt,
    const float* __restrict__ bias, float* __restrict__ C,
    int K, int rowBase, int colBase)
{
    __nv_bfloat16* sAhi = (__nv_bfloat16*)sm;
    __nv_bfloat16* sAlo = sAhi + 128 * ROWE;
    __nv_bfloat16* sBhi = sAlo + 128 * ROWE;
    __nv_bfloat16* sBlo = sBhi + 128 * ROWE;

    const int tid = threadIdx.x;
    const int wid = tid >> 5;
    const int lane = tid & 31;
    const int gid = lane >> 2;
    const int tig = lane & 3;

    const int m0 = (wid & 1) * 64;
    const int n0 = (wid >> 1) * 32;

    const uint32_t uAhi = smem_u32(sAhi), uAlo = smem_u32(sAlo);
    const uint32_t uBhi = smem_u32(sBhi), uBlo = smem_u32(sBlo);

    const int q = lane >> 3, ri = lane & 7;
    const uint32_t aOff = (uint32_t)(m0 + (q & 1) * 8 + ri) * ROWB + (q >> 1) * 16;
    const uint32_t bOff = (uint32_t)(n0 + (q >> 1) * 8 + ri) * ROWB + (q & 1) * 16;

    const int ldRow = tid >> 3;
    const int ldC4  = (tid & 7) * 4;

    float acc[4][4][4];
    #pragma unroll
    for (int mt = 0; mt < 4; mt++)
        #pragma unroll
        for (int nt = 0; nt < 4; nt++)
            #pragma unroll
            for (int e = 0; e < 4; e++) acc[mt][nt][e] = 0.f;

    for (int k0 = 0; k0 < K; k0 += 32) {
        // ---- load + split-convert A tile (128 x 32 fp32) ----
        #pragma unroll
        for (int l = 0; l < 4; l++) {
            int r = ldRow + l * 32;
            float4 v = *(const float4*)(A + (size_t)(rowBase + r) * K + k0 + ldC4);
            __nv_bfloat16 h0 = __float2bfloat16_rn(v.x);
            __nv_bfloat16 h1 = __float2bfloat16_rn(v.y);
            __nv_bfloat16 h2 = __float2bfloat16_rn(v.z);
            __nv_bfloat16 h3 = __float2bfloat16_rn(v.w);
            __nv_bfloat16 l0 = __float2bfloat16_rn(v.x - __bfloat162float(h0));
            __nv_bfloat16 l1 = __float2bfloat16_rn(v.y - __bfloat162float(h1));
            __nv_bfloat16 l2 = __float2bfloat16_rn(v.z - __bfloat162float(h2));
            __nv_bfloat16 l3 = __float2bfloat16_rn(v.w - __bfloat162float(h3));
            __nv_bfloat162 hA(h0, h1), hB(h2, h3), lA(l0, l1), lB(l2, l3);
            int o = r * ROWE + ldC4;
            *(uint2*)&sAhi[o] = make_uint2(*(uint32_t*)&hA, *(uint32_t*)&hB);
            *(uint2*)&sAlo[o] = make_uint2(*(uint32_t*)&lA, *(uint32_t*)&lB);
        }
        // ---- load + split-convert B tile (128 x 32 fp32 of Wt) ----
        #pragma unroll
        for (int l = 0; l < 4; l++) {
            int r = ldRow + l * 32;
            float4 v = *(const float4*)(Wt + (size_t)(colBase + r) * K + k0 + ldC4);
            __nv_bfloat16 h0 = __float2bfloat16_rn(v.x);
            __nv_bfloat16 h1 = __float2bfloat16_rn(v.y);
            __nv_bfloat16 h2 = __float2bfloat16_rn(v.z);
            __nv_bfloat16 h3 = __float2bfloat16_rn(v.w);
            __nv_bfloat16 l0 = __float2bfloat16_rn(v.x - __bfloat162float(h0));
            __nv_bfloat16 l1 = __float2bfloat16_rn(v.y - __bfloat162float(h1));
            __nv_bfloat16 l2 = __float2bfloat16_rn(v.z - __bfloat162float(h2));
            __nv_bfloat16 l3 = __float2bfloat16_rn(v.w - __bfloat162float(h3));
            __nv_bfloat162 hA(h0, h1), hB(h2, h3), lA(l0, l1), lB(l2, l3);
            int o = r * ROWE + ldC4;
            *(uint2*)&sBhi[o] = make_uint2(*(uint32_t*)&hA, *(uint32_t*)&hB);
            *(uint2*)&sBlo[o] = make_uint2(*(uint32_t*)&lA, *(uint32_t*)&lB);
        }
        __syncthreads();

        // ---- MMA: 2 k16 steps, 4 m-tiles x 4 n-tiles, 3 split terms ----
        #pragma unroll
        for (int kk = 0; kk < 2; kk++) {
            uint32_t bh[4][2], bl[4][2];
            #pragma unroll
            for (int p = 0; p < 2; p++) {
                uint32_t r4[4];
                ldmx4(uBhi + bOff + p * 16 * ROWB + kk * 32, r4);
                bh[2 * p][0] = r4[0]; bh[2 * p][1] = r4[1];
                bh[2 * p + 1][0] = r4[2]; bh[2 * p + 1][1] = r4[3];
                ldmx4(uBlo + bOff + p * 16 * ROWB + kk * 32, r4);
                bl[2 * p][0] = r4[0]; bl[2 * p][1] = r4[1];
                bl[2 * p + 1][0] = r4[2]; bl[2 * p + 1][1] = r4[3];
            }
            #pragma unroll
            for (int mt = 0; mt < 4; mt++) {
                uint32_t ah[4], al[4];
                ldmx4(uAhi + aOff + mt * 16 * ROWB + kk * 32, ah);
                ldmx4(uAlo + aOff + mt * 16 * ROWB + kk * 32, al);
                #pragma unroll
                for (int nt = 0; nt < 4; nt++) {
                    mma16816(acc[mt][nt], ah, bh[nt]);
                    mma16816(acc[mt][nt], ah, bl[nt]);
                    mma16816(acc[mt][nt], al, bh[nt]);
                }
            }
        }
        __syncthreads();
    }

    // ---- epilogue: acc + bias -> C ----
    #pragma unroll
    for (int nt = 0; nt < 4; nt++) {
        const int cg = colBase + n0 + nt * 8 + tig * 2;
        float2 bv = *(const float2*)(bias + cg);
        #pragma unroll
        for (int mt = 0; mt < 4; mt++) {
            int rg0 = rowBase + m0 + mt * 16 + gid;
            float2 v0 = make_float2(acc[mt][nt][0] + bv.x, acc[mt][nt][1] + bv.y);
            float2 v1 = make_float2(acc[mt][nt][2] + bv.x, acc[mt][nt][3] + bv.y);
            *(float2*)(C + (size_t)rg0 * OUTP + cg) = v0;
            *(float2*)(C + (size_t)(rg0 + 8) * OUTP + cg) = v1;
        }
    }
}

// ---------------------------------------------------------------------------
// knn body (R3 proven scan): one CTA handles 256 query points of batch b.
__device__ __forceinline__ void knn_body(
    char* sm, const float* __restrict__ p1, const float* __restrict__ p2, int bx)
{
    float4* sp = (float4*)sm;             // 2048 * 16B = 32KB (fits 40KB)
    const int b     = bx >> 5;
    const int chunk = bx & 31;

    const float* P2 = p2 + (size_t)b * N2 * 3;
    for (int i = threadIdx.x; i < N2; i += 256) {
        float x = P2[i * 3 + 0], y = P2[i * 3 + 1], z = P2[i * 3 + 2];
        sp[i] = make_float4(x, y, z, fmaf(x, x, fmaf(y, y, z * z)));
    }
    __syncthreads();

    const int n = chunk * 256 + threadIdx.x;
    const float* P1 = p1 + ((size_t)b * N1 + n) * 3;
    const float px = P1[0], py = P1[1], pz = P1[2];
    const float s1 = fmaf(px, px, fmaf(py, py, pz * pz));

    float d0 = 1e30f, d1 = 1e30f, d2 = 1e30f;
    int   i0 = 0,     i1 = 0,     i2 = 0;

    #pragma unroll 4
    for (int j = 0; j < N2; j++) {
        float4 qq = sp[j];
        float dot = fmaf(px, qq.x, fmaf(py, qq.y, pz * qq.z));
        float d = (s1 + qq.w) - 2.f * dot;
        if (d < d2) {
            if (d < d1) {
                d2 = d1; i2 = i1;
                if (d < d0) { d1 = d0; i1 = i0; d0 = d; i0 = j; }
                else        { d1 = d;  i1 = j; }
            } else { d2 = d; i2 = j; }
        }
    }

    float r0 = 1.f / (d0 + 1e-8f);
    float r1 = 1.f / (d1 + 1e-8f);
    float r2 = 1.f / (d2 + 1e-8f);
    float rs = 1.f / (r0 + r1 + r2);

    size_t o = ((size_t)b * N1 + n) * 3;
    g_idx[o + 0] = b * N2 + i0;
    g_idx[o + 1] = b * N2 + i1;
    g_idx[o + 2] = b * N2 + i2;
    g_w[o + 0] = r0 * rs;
    g_w[o + 1] = r1 * rs;
    g_w[o + 2] = r2 * rs;
}

// ---------------------------------------------------------------------------
// Mega-kernel: GEMM2 CTAs (longest first), then GEMM1 CTAs, then knn CTAs.
// All branches 256 threads, shared 40KB smem union, branch on blockIdx only.
__global__ __launch_bounds__(256) void mega_kernel(
    const float* __restrict__ x2, const float* __restrict__ wt2,
    const float* __restrict__ b2, float* __restrict__ y2,
    const float* __restrict__ x1, const float* __restrict__ wt1,
    const float* __restrict__ b1, float* __restrict__ y1,
    const float* __restrict__ p1, const float* __restrict__ p2)
{
    __shared__ __align__(16) char sm[4 * 128 * ROWB];   // 40960 bytes
    int bx = blockIdx.x;
    if (bx < GEMM2_CTAS) {
        gemm_body(sm, x2, wt2, b2, y2, INP, (bx >> 1) * 128, (bx & 1) * 128);
    } else if (bx < GEMM2_CTAS + GEMM1_CTAS) {
        int t = bx - GEMM2_CTAS;
        gemm_body(sm, x1, wt1, b1, y1, OUTP, (t >> 1) * 128, (t & 1) * 128);
    } else {
        knn_body(sm, p1, p2, bx - (GEMM2_CTAS + GEMM1_CTAS));
    }
}

// ---------------------------------------------------------------------------
__global__ __launch_bounds__(256) void stats_kernel(
    const float* __restrict__ y, int rows, float* __restrict__ stats)
{
    int c = threadIdx.x;
    float s = 0.f, q = 0.f;
    for (int r = blockIdx.x; r < rows; r += gridDim.x) {
        float v = y[(size_t)r * OUTP + c];
        s += v;
        q = fmaf(v, v, q);
    }
    atomicAdd(&stats[c], s);
    atomicAdd(&stats[OUTP + c], q);
}

__global__ void finalize_kernel(const float* __restrict__ stats,
                                const float* __restrict__ gamma,
                                const float* __restrict__ beta,
                                float inv_count, float* __restrict__ ab)
{
    int c = threadIdx.x;
    float mean = stats[c] * inv_count;
    float var  = stats[OUTP + c] * inv_count - mean * mean;
    float scale = gamma[c] * rsqrtf(var + 1e-5f);
    ab[c]        = scale;
    ab[OUTP + c] = beta[c] - mean * scale;
}

// ---------------------------------------------------------------------------
__global__ __launch_bounds__(256) void out_kernel(float* __restrict__ out)
{
    const int r = blockIdx.x;
    const int c = threadIdx.x;

    const float a1 = g_ab1[c], s1 = g_ab1[OUTP + c];
    const float a2 = g_ab2[c], s2 = g_ab2[OUTP + c];

    const size_t o3 = (size_t)r * 3;
    const int   j0 = g_idx[o3 + 0], j1 = g_idx[o3 + 1], j2 = g_idx[o3 + 2];
    const float w0 = g_w[o3 + 0],   w1 = g_w[o3 + 1],   w2 = g_w[o3 + 2];

    float v1 = fmaxf(fmaf(g_y1[(size_t)r * OUTP + c], a1, s1), 0.f);
    float h0 = fmaxf(fmaf(g_y2[(size_t)j0 * OUTP + c], a2, s2), 0.f);
    float h1 = fmaxf(fmaf(g_y2[(size_t)j1 * OUTP + c], a2, s2), 0.f);
    float h2 = fmaxf(fmaf(g_y2[(size_t)j2 * OUTP + c], a2, s2), 0.f);

    out[(size_t)r * OUTP + c] = v1 + fmaf(w0, h0, fmaf(w1, h1, w2 * h2));
}

// ---------------------------------------------------------------------------
extern "C" void kernel_launch(void* const* d_in, const int* in_sizes, int n_in,
                              void* d_out, int out_size)
{
    const float* p1     = (const float*)d_in[0];
    const float* x1     = (const float*)d_in[1];
    const float* p2     = (const float*)d_in[2];
    const float* x2     = (const float*)d_in[3];
    const float* W1     = (const float*)d_in[4];
    const float* b1     = (const float*)d_in[5];
    const float* gamma1 = (const float*)d_in[6];
    const float* beta1  = (const float*)d_in[7];
    const float* W2     = (const float*)d_in[8];
    const float* b2     = (const float*)d_in[9];
    const float* gamma2 = (const float*)d_in[10];
    const float* beta2  = (const float*)d_in[11];
    float* out = (float*)d_out;

    float *y1, *y2, *st1, *st2, *ab1, *ab2, *wt1, *wt2;
    cudaGetSymbolAddress((void**)&y1,  g_y1);
    cudaGetSymbolAddress((void**)&y2,  g_y2);
    cudaGetSymbolAddress((void**)&st1, g_stats1);
    cudaGetSymbolAddress((void**)&st2, g_stats2);
    cudaGetSymbolAddress((void**)&ab1, g_ab1);
    cudaGetSymbolAddress((void**)&ab2, g_ab2);
    cudaGetSymbolAddress((void**)&wt1, g_Wt1);
    cudaGetSymbolAddress((void**)&wt2, g_Wt2);

    zero_stats_kernel<<<1, 512>>>();

    // Transpose weights into [N,K]
    transpose_kernel<<<dim3(OUTP / 32, INP / 32), dim3(32, 8)>>>(W2, wt2, INP, OUTP);
    transpose_kernel<<<dim3(OUTP / 32, OUTP / 32), dim3(32, 8)>>>(W1, wt1, OUTP, OUTP);

    // One launch: GEMM2 + GEMM1 + knn (768 CTAs, LPT-ordered)
    mega_kernel<<<GEMM2_CTAS + GEMM1_CTAS + KNN_CTAS, 256>>>(
        x2, wt2, b2, y2, x1, wt1, b1, y1, p1, p2);

    stats_kernel<<<512, 256>>>(y2, M2, st2);
    stats_kernel<<<2048, 256>>>(y1, M1, st1);

    finalize_kernel<<<1, 256>>>(st2, gamma2, beta2, 1.f / (float)M2, ab2);
    finalize_kernel<<<1, 256>>>(st1, gamma1, beta1, 1.f / (float)M1, ab1);

    knn_kernel_unused:;  // (label no-op to keep diff minimal)

    out_kernel<<<M1, 256>>>(out);
}

// round 11
// speedup vs baseline: 1.2822x; 1.0662x over previous
#include <cuda_runtime.h>
#include <cuda_bf16.h>
#include <cstdint>

// Problem constants
#define BB 4
#define N1 8192
#define N2 2048
#define INP 512
#define OUTP 256
#define M1 (BB * N1)   // 32768
#define M2 (BB * N2)   // 8192

// Device scratch
__device__ float g_y1[M1 * OUTP];     // x1@W1+b1  (32 MB)
__device__ float g_y2[M2 * OUTP];     // x2@W2+b2  (8 MB)
__device__ float g_Wt1[OUTP * OUTP];  // W1^T  [N,K]
__device__ float g_Wt2[OUTP * INP];   // W2^T  [N,K]
__device__ float g_stats1[2 * OUTP];
__device__ float g_stats2[2 * OUTP];
__device__ float g_ab1[2 * OUTP];
__device__ float g_ab2[2 * OUTP];
__device__ int   g_idx[BB * N1 * 3];
__device__ float g_w[BB * N1 * 3];

// smem row stride for tf32 tiles: 36 words = 144 bytes.
// 8 consecutive rows hit 8 distinct 16B bank-groups (144*r mod 128 = 16r).
#define SW 36

// ---------------------------------------------------------------------------
__device__ __forceinline__ uint32_t smem_u32(const void* p) {
    uint32_t a;
    asm("{ .reg .u64 t; cvta.to.shared.u64 t, %1; cvt.u32.u64 %0, t; }"
        : "=r"(a) : "l"(p));
    return a;
}

__device__ __forceinline__ void ldmx4(uint32_t addr, uint32_t* r) {
    asm volatile("ldmatrix.sync.aligned.m8n8.x4.shared.b16 {%0,%1,%2,%3}, [%4];"
                 : "=r"(r[0]), "=r"(r[1]), "=r"(r[2]), "=r"(r[3]) : "r"(addr));
}

// m16n8k8 tf32 MMA, fp32 accumulate
__device__ __forceinline__ void mma_tf32(float* c, const uint32_t* a,
                                         const uint32_t* b) {
    asm volatile(
        "mma.sync.aligned.m16n8k8.row.col.f32.tf32.tf32.f32 "
        "{%0,%1,%2,%3}, {%4,%5,%6,%7}, {%8,%9}, {%0,%1,%2,%3};"
        : "+f"(c[0]), "+f"(c[1]), "+f"(c[2]), "+f"(c[3])
        : "r"(a[0]), "r"(a[1]), "r"(a[2]), "r"(a[3]), "r"(b[0]), "r"(b[1]));
}

__device__ __forceinline__ uint32_t f2tf32(float x) {
    uint32_t r;
    asm("cvt.rna.tf32.f32 %0, %1;" : "=r"(r) : "f"(x));
    return r;
}

// ---------------------------------------------------------------------------
__global__ void zero_stats_kernel() {
    int t = threadIdx.x;
    if (t < 2 * OUTP) { g_stats1[t] = 0.f; g_stats2[t] = 0.f; }
}

// Tiled transpose: dst[C][R] = src[R][C]^T. block (32,8), grid (C/32, R/32)
__global__ __launch_bounds__(256) void transpose_kernel(
    const float* __restrict__ src, float* __restrict__ dst, int R, int C)
{
    __shared__ float t[32][33];
    int bx = blockIdx.x * 32, by = blockIdx.y * 32;
    int x = bx + threadIdx.x;
    #pragma unroll
    for (int i = 0; i < 32; i += 8)
        t[threadIdx.y + i][threadIdx.x] = src[(size_t)(by + threadIdx.y + i) * C + x];
    __syncthreads();
    int x2 = by + threadIdx.x;
    #pragma unroll
    for (int i = 0; i < 32; i += 8)
        dst[(size_t)(bx + threadIdx.y + i) * R + x2] = t[threadIdx.x][threadIdx.y + i];
}

// ---------------------------------------------------------------------------
// Single-pass TF32 HMMA GEMM: C[M,256] = A[M,K] @ Wt[256,K]^T + bias
// CTA tile 128x128, BK=32, 8 warps (warp tile 64x32), m16n8k8 tf32 MMA.
// Operands converted to tf32 (rna) at the smem-store stage; fragments loaded
// via ldmatrix.b16 (an 8x8 b16 tile == 8x4 tf32 tile; lane->(row=l>>2,col=l&3)
// matches the tf32 fragment layout exactly).
template<int K>
__global__ __launch_bounds__(256) void gemm_tf32_kernel(
    const float* __restrict__ A, const float* __restrict__ Wt,
    const float* __restrict__ bias, float* __restrict__ C)
{
    __shared__ uint32_t sA[128 * SW];
    __shared__ uint32_t sB[128 * SW];

    const int tid = threadIdx.x;
    const int wid = tid >> 5;
    const int lane = tid & 31;
    const int gid = lane >> 2;
    const int tig = lane & 3;

    const int rowBase = blockIdx.y * 128;
    const int colBase = blockIdx.x * 128;
    const int m0 = (wid & 1) * 64;
    const int n0 = (wid >> 1) * 32;

    // ldmatrix per-lane base address (bytes):
    //  lanes 0-7: rows r..r+7 (k lo16B); 8-15: rows+8; 16-23: rows, k hi16B; 24-31: rows+8, hi.
    const int lrow = ((lane >> 3) & 1) * 8 + (lane & 7);
    const int lc16 = (lane >> 4) * 16;
    const uint32_t aBase = smem_u32(sA) + (uint32_t)(m0 + lrow) * 144 + lc16;
    const uint32_t bBase = smem_u32(sB) + (uint32_t)(n0 + lrow) * 144 + lc16;

    // loader indices: 256 threads cover 32 rows x 32 k per step
    const int ldRow = tid >> 3;
    const int ldC4  = (tid & 7) * 4;

    float acc[4][4][4];
    #pragma unroll
    for (int mt = 0; mt < 4; mt++)
        #pragma unroll
        for (int nt = 0; nt < 4; nt++)
            #pragma unroll
            for (int e = 0; e < 4; e++) acc[mt][nt][e] = 0.f;

    for (int k0 = 0; k0 < K; k0 += 32) {
        // ---- load + tf32-convert A tile (128 x 32 fp32) ----
        #pragma unroll
        for (int l = 0; l < 4; l++) {
            int r = ldRow + l * 32;
            float4 v = *(const float4*)(A + (size_t)(rowBase + r) * K + k0 + ldC4);
            uint4 t;
            t.x = f2tf32(v.x); t.y = f2tf32(v.y);
            t.z = f2tf32(v.z); t.w = f2tf32(v.w);
            *(uint4*)&sA[r * SW + ldC4] = t;
        }
        // ---- load + tf32-convert B tile (128 x 32 fp32 of Wt) ----
        #pragma unroll
        for (int l = 0; l < 4; l++) {
            int r = ldRow + l * 32;
            float4 v = *(const float4*)(Wt + (size_t)(colBase + r) * K + k0 + ldC4);
            uint4 t;
            t.x = f2tf32(v.x); t.y = f2tf32(v.y);
            t.z = f2tf32(v.z); t.w = f2tf32(v.w);
            *(uint4*)&sB[r * SW + ldC4] = t;
        }
        __syncthreads();

        // ---- MMA: 4 k8 steps, 4 m-tiles x 4 n-tiles ----
        #pragma unroll
        for (int kt = 0; kt < 4; kt++) {
            uint32_t b[4][2];
            #pragma unroll
            for (int np = 0; np < 2; np++) {
                uint32_t r4[4];
                ldmx4(bBase + np * (16 * 144) + kt * 32, r4);
                b[np * 2][0]     = r4[0];   // b0 of n-tile np*2
                b[np * 2 + 1][0] = r4[1];   // b0 of n-tile np*2+1
                b[np * 2][1]     = r4[2];   // b1 of n-tile np*2
                b[np * 2 + 1][1] = r4[3];   // b1 of n-tile np*2+1
            }
            #pragma unroll
            for (int mt = 0; mt < 4; mt++) {
                uint32_t a[4];
                ldmx4(aBase + mt * (16 * 144) + kt * 32, a);
                #pragma unroll
                for (int nt = 0; nt < 4; nt++)
                    mma_tf32(acc[mt][nt], a, b[nt]);
            }
        }
        __syncthreads();
    }

    // ---- epilogue: acc + bias -> C (same fragment layout as m16n8k16) ----
    #pragma unroll
    for (int nt = 0; nt < 4; nt++) {
        const int cg = colBase + n0 + nt * 8 + tig * 2;
        float2 bv = *(const float2*)(bias + cg);
        #pragma unroll
        for (int mt = 0; mt < 4; mt++) {
            int rg0 = rowBase + m0 + mt * 16 + gid;
            float2 v0 = make_float2(acc[mt][nt][0] + bv.x, acc[mt][nt][1] + bv.y);
            float2 v1 = make_float2(acc[mt][nt][2] + bv.x, acc[mt][nt][3] + bv.y);
            *(float2*)(C + (size_t)rg0 * OUTP + cg) = v0;
            *(float2*)(C + (size_t)(rg0 + 8) * OUTP + cg) = v1;
        }
    }
}

// ---------------------------------------------------------------------------
__global__ __launch_bounds__(256) void stats_kernel(
    const float* __restrict__ y, int rows, float* __restrict__ stats)
{
    int c = threadIdx.x;
    float s = 0.f, q = 0.f;
    for (int r = blockIdx.x; r < rows; r += gridDim.x) {
        float v = y[(size_t)r * OUTP + c];
        s += v;
        q = fmaf(v, v, q);
    }
    atomicAdd(&stats[c], s);
    atomicAdd(&stats[OUTP + c], q);
}

__global__ void finalize_kernel(const float* __restrict__ stats,
                                const float* __restrict__ gamma,
                                const float* __restrict__ beta,
                                float inv_count, float* __restrict__ ab)
{
    int c = threadIdx.x;
    float mean = stats[c] * inv_count;
    float var  = stats[OUTP + c] * inv_count - mean * mean;
    float scale = gamma[c] * rsqrtf(var + 1e-5f);
    ab[c]        = scale;
    ab[OUTP + c] = beta[c] - mean * scale;
}

// ---------------------------------------------------------------------------
// 3-NN (R3 proven scan)
__global__ __launch_bounds__(256) void knn_kernel(
    const float* __restrict__ p1, const float* __restrict__ p2)
{
    __shared__ float4 sp[N2];
    const int b     = blockIdx.x >> 5;
    const int chunk = blockIdx.x & 31;

    const float* P2 = p2 + (size_t)b * N2 * 3;
    for (int i = threadIdx.x; i < N2; i += 256) {
        float x = P2[i * 3 + 0], y = P2[i * 3 + 1], z = P2[i * 3 + 2];
        sp[i] = make_float4(x, y, z, fmaf(x, x, fmaf(y, y, z * z)));
    }
    __syncthreads();

    const int n = chunk * 256 + threadIdx.x;
    const float* P1 = p1 + ((size_t)b * N1 + n) * 3;
    const float px = P1[0], py = P1[1], pz = P1[2];
    const float s1 = fmaf(px, px, fmaf(py, py, pz * pz));

    float d0 = 1e30f, d1 = 1e30f, d2 = 1e30f;
    int   i0 = 0,     i1 = 0,     i2 = 0;

    #pragma unroll 4
    for (int j = 0; j < N2; j++) {
        float4 qq = sp[j];
        float dot = fmaf(px, qq.x, fmaf(py, qq.y, pz * qq.z));
        float d = (s1 + qq.w) - 2.f * dot;
        if (d < d2) {
            if (d < d1) {
                d2 = d1; i2 = i1;
                if (d < d0) { d1 = d0; i1 = i0; d0 = d; i0 = j; }
                else        { d1 = d;  i1 = j; }
            } else { d2 = d; i2 = j; }
        }
    }

    float r0 = 1.f / (d0 + 1e-8f);
    float r1 = 1.f / (d1 + 1e-8f);
    float r2 = 1.f / (d2 + 1e-8f);
    float rs = 1.f / (r0 + r1 + r2);

    size_t o = ((size_t)b * N1 + n) * 3;
    g_idx[o + 0] = b * N2 + i0;
    g_idx[o + 1] = b * N2 + i1;
    g_idx[o + 2] = b * N2 + i2;
    g_w[o + 0] = r0 * rs;
    g_w[o + 1] = r1 * rs;
    g_w[o + 2] = r2 * rs;
}

// ---------------------------------------------------------------------------
__global__ __launch_bounds__(256) void out_kernel(float* __restrict__ out)
{
    const int r = blockIdx.x;
    const int c = threadIdx.x;

    const float a1 = g_ab1[c], s1 = g_ab1[OUTP + c];
    const float a2 = g_ab2[c], s2 = g_ab2[OUTP + c];

    const size_t o3 = (size_t)r * 3;
    const int   j0 = g_idx[o3 + 0], j1 = g_idx[o3 + 1], j2 = g_idx[o3 + 2];
    const float w0 = g_w[o3 + 0],   w1 = g_w[o3 + 1],   w2 = g_w[o3 + 2];

    float v1 = fmaxf(fmaf(g_y1[(size_t)r * OUTP + c], a1, s1), 0.f);
    float h0 = fmaxf(fmaf(g_y2[(size_t)j0 * OUTP + c], a2, s2), 0.f);
    float h1 = fmaxf(fmaf(g_y2[(size_t)j1 * OUTP + c], a2, s2), 0.f);
    float h2 = fmaxf(fmaf(g_y2[(size_t)j2 * OUTP + c], a2, s2), 0.f);

    out[(size_t)r * OUTP + c] = v1 + fmaf(w0, h0, fmaf(w1, h1, w2 * h2));
}

// ---------------------------------------------------------------------------
extern "C" void kernel_launch(void* const* d_in, const int* in_sizes, int n_in,
                              void* d_out, int out_size)
{
    const float* p1     = (const float*)d_in[0];
    const float* x1     = (const float*)d_in[1];
    const float* p2     = (const float*)d_in[2];
    const float* x2     = (const float*)d_in[3];
    const float* W1     = (const float*)d_in[4];
    const float* b1     = (const float*)d_in[5];
    const float* gamma1 = (const float*)d_in[6];
    const float* beta1  = (const float*)d_in[7];
    const float* W2     = (const float*)d_in[8];
    const float* b2     = (const float*)d_in[9];
    const float* gamma2 = (const float*)d_in[10];
    const float* beta2  = (const float*)d_in[11];
    float* out = (float*)d_out;

    float *y1, *y2, *st1, *st2, *ab1, *ab2, *wt1, *wt2;
    cudaGetSymbolAddress((void**)&y1,  g_y1);
    cudaGetSymbolAddress((void**)&y2,  g_y2);
    cudaGetSymbolAddress((void**)&st1, g_stats1);
    cudaGetSymbolAddress((void**)&st2, g_stats2);
    cudaGetSymbolAddress((void**)&ab1, g_ab1);
    cudaGetSymbolAddress((void**)&ab2, g_ab2);
    cudaGetSymbolAddress((void**)&wt1, g_Wt1);
    cudaGetSymbolAddress((void**)&wt2, g_Wt2);

    zero_stats_kernel<<<1, 512>>>();

    // Transpose weights into [N,K]
    transpose_kernel<<<dim3(OUTP / 32, INP / 32), dim3(32, 8)>>>(W2, wt2, INP, OUTP);
    transpose_kernel<<<dim3(OUTP / 32, OUTP / 32), dim3(32, 8)>>>(W1, wt1, OUTP, OUTP);

    // Single-pass TF32 HMMA GEMMs
    gemm_tf32_kernel<INP><<<dim3(2, M2 / 128), 256>>>(x2, wt2, b2, y2);
    gemm_tf32_kernel<OUTP><<<dim3(2, M1 / 128), 256>>>(x1, wt1, b1, y1);

    stats_kernel<<<512, 256>>>(y2, M2, st2);
    stats_kernel<<<2048, 256>>>(y1, M1, st1);

    finalize_kernel<<<1, 256>>>(st2, gamma2, beta2, 1.f / (float)M2, ab2);
    finalize_kernel<<<1, 256>>>(st1, gamma1, beta1, 1.f / (float)M1, ab1);

    knn_kernel<<<BB * (N1 / 256), 256>>>(p1, p2);

    out_kernel<<<M1, 256>>>(out);
}

// round 12
// speedup vs baseline: 1.3413x; 1.0460x over previous
#include <cuda_runtime.h>
#include <cstdint>

// Problem constants
#define BB 4
#define N1 8192
#define N2 2048
#define INP 512
#define OUTP 256
#define M1 (BB * N1)   // 32768
#define M2 (BB * N2)   // 8192

// Device scratch
__device__ float g_y1[M1 * OUTP];     // x1@W1+b1  (32 MB)
__device__ float g_y2[M2 * OUTP];     // x2@W2+b2  (8 MB)
__device__ float g_Wt1[OUTP * OUTP];  // W1^T  [N,K]
__device__ float g_Wt2[OUTP * INP];   // W2^T  [N,K]
__device__ float g_stats1[2 * OUTP];
__device__ float g_stats2[2 * OUTP];
__device__ float g_ab1[2 * OUTP];
__device__ float g_ab2[2 * OUTP];
__device__ int   g_idx[BB * N1 * 3];
__device__ float g_w[BB * N1 * 3];

// smem row stride for tf32 tiles: 36 words = 144 bytes.
// 8 consecutive rows hit 8 distinct 16B bank-groups (144*r mod 128 = 16r).
#define SW 36
#define STAGE_WORDS (2 * 128 * SW)          // A + B per stage = 9216 words
#define STAGE_BYTES (STAGE_WORDS * 4)       // 36864
#define B_OFF_BYTES (128 * SW * 4)          // 18432
#define GEMM_SMEM   (2 * STAGE_BYTES)       // 73728

// ---------------------------------------------------------------------------
__device__ __forceinline__ uint32_t smem_u32(const void* p) {
    uint32_t a;
    asm("{ .reg .u64 t; cvta.to.shared.u64 t, %1; cvt.u32.u64 %0, t; }"
        : "=r"(a) : "l"(p));
    return a;
}

__device__ __forceinline__ void ldmx4(uint32_t addr, uint32_t* r) {
    asm volatile("ldmatrix.sync.aligned.m8n8.x4.shared.b16 {%0,%1,%2,%3}, [%4];"
                 : "=r"(r[0]), "=r"(r[1]), "=r"(r[2]), "=r"(r[3]) : "r"(addr));
}

// m16n8k8 tf32 MMA, fp32 accumulate
__device__ __forceinline__ void mma_tf32(float* c, const uint32_t* a,
                                         const uint32_t* b) {
    asm volatile(
        "mma.sync.aligned.m16n8k8.row.col.f32.tf32.tf32.f32 "
        "{%0,%1,%2,%3}, {%4,%5,%6,%7}, {%8,%9}, {%0,%1,%2,%3};"
        : "+f"(c[0]), "+f"(c[1]), "+f"(c[2]), "+f"(c[3])
        : "r"(a[0]), "r"(a[1]), "r"(a[2]), "r"(a[3]), "r"(b[0]), "r"(b[1]));
}

__device__ __forceinline__ void cpasync16(uint32_t d, const void* s) {
    asm volatile("cp.async.cg.shared.global [%0], [%1], 16;"
                 :: "r"(d), "l"(s) : "memory");
}
#define CP_COMMIT() asm volatile("cp.async.commit_group;" ::: "memory")
#define CP_WAIT1()  asm volatile("cp.async.wait_group 1;" ::: "memory")

// ---------------------------------------------------------------------------
__global__ void zero_stats_kernel() {
    int t = threadIdx.x;
    if (t < 2 * OUTP) { g_stats1[t] = 0.f; g_stats2[t] = 0.f; }
}

// Tiled transpose: dst[C][R] = src[R][C]^T. block (32,8), grid (C/32, R/32)
__global__ __launch_bounds__(256) void transpose_kernel(
    const float* __restrict__ src, float* __restrict__ dst, int R, int C)
{
    __shared__ float t[32][33];
    int bx = blockIdx.x * 32, by = blockIdx.y * 32;
    int x = bx + threadIdx.x;
    #pragma unroll
    for (int i = 0; i < 32; i += 8)
        t[threadIdx.y + i][threadIdx.x] = src[(size_t)(by + threadIdx.y + i) * C + x];
    __syncthreads();
    int x2 = by + threadIdx.x;
    #pragma unroll
    for (int i = 0; i < 32; i += 8)
        dst[(size_t)(bx + threadIdx.y + i) * R + x2] = t[threadIdx.x][threadIdx.y + i];
}

// ---------------------------------------------------------------------------
// TF32 HMMA GEMM, cp.async double-buffered: C[M,256] = A[M,K]@Wt[256,K]^T + bias.
// CTA tile 128x128, BK=32, 8 warps (warp tile 64x32), m16n8k8 tf32 MMA.
// Raw fp32 bits are used as tf32 operands (HW uses high mantissa bits only),
// so tiles stream gmem->smem via cp.async with ZERO in-loop conversion.
template<int K>
__global__ __launch_bounds__(256) void gemm_tf32_pipe_kernel(
    const float* __restrict__ A, const float* __restrict__ Wt,
    const float* __restrict__ bias, float* __restrict__ C)
{
    extern __shared__ uint32_t smem[];
    const uint32_t base_u = smem_u32(smem);
    constexpr int NCH = K / 32;

    const int tid = threadIdx.x;
    const int wid = tid >> 5;
    const int lane = tid & 31;
    const int gid = lane >> 2;
    const int tig = lane & 3;

    const int rowBase = blockIdx.y * 128;
    const int colBase = blockIdx.x * 128;
    const int m0 = (wid & 1) * 64;
    const int n0 = (wid >> 1) * 32;

    // ldmatrix per-lane components (proven in R11)
    const int lrow = ((lane >> 3) & 1) * 8 + (lane & 7);
    const int lc16 = (lane >> 4) * 16;
    const uint32_t aLane = (uint32_t)(m0 + lrow) * 144 + lc16;
    const uint32_t bLane = (uint32_t)(n0 + lrow) * 144 + lc16 + B_OFF_BYTES;

    // loader indices: 1024 16B chunks per operand tile, 4 per thread
    const int ldRow = tid >> 3;
    const int ldC = tid & 7;

    float acc[4][4][4];
    #pragma unroll
    for (int mt = 0; mt < 4; mt++)
        #pragma unroll
        for (int nt = 0; nt < 4; nt++)
            #pragma unroll
            for (int e = 0; e < 4; e++) acc[mt][nt][e] = 0.f;

    auto issue_stage = [&](int slot, int k0) {
        const uint32_t st = base_u + slot * STAGE_BYTES;
        #pragma unroll
        for (int l = 0; l < 4; l++) {
            int r = ldRow + l * 32;
            uint32_t d = st + (uint32_t)r * 144 + ldC * 16;
            cpasync16(d, A + (size_t)(rowBase + r) * K + k0 + ldC * 4);
            cpasync16(d + B_OFF_BYTES, Wt + (size_t)(colBase + r) * K + k0 + ldC * 4);
        }
        CP_COMMIT();
    };

    issue_stage(0, 0);
    issue_stage(1, 32);

    for (int c = 0; c < NCH; c++) {
        CP_WAIT1();
        __syncthreads();
        const uint32_t st = base_u + (c & 1) * STAGE_BYTES;
        const uint32_t aBase = st + aLane;
        const uint32_t bBase = st + bLane;

        // ---- MMA: 4 k8 steps, 4 m-tiles x 4 n-tiles ----
        #pragma unroll
        for (int kt = 0; kt < 4; kt++) {
            uint32_t b[4][2];
            #pragma unroll
            for (int np = 0; np < 2; np++) {
                uint32_t r4[4];
                ldmx4(bBase + np * (16 * 144) + kt * 32, r4);
                b[np * 2][0]     = r4[0];
                b[np * 2 + 1][0] = r4[1];
                b[np * 2][1]     = r4[2];
                b[np * 2 + 1][1] = r4[3];
            }
            #pragma unroll
            for (int mt = 0; mt < 4; mt++) {
                uint32_t a[4];
                ldmx4(aBase + mt * (16 * 144) + kt * 32, a);
                #pragma unroll
                for (int nt = 0; nt < 4; nt++)
                    mma_tf32(acc[mt][nt], a, b[nt]);
            }
        }
        __syncthreads();
        if (c + 2 < NCH) issue_stage(c & 1, (c + 2) * 32);
        else CP_COMMIT();   // keep wait_group accounting uniform
    }

    // ---- epilogue: acc + bias -> C ----
    #pragma unroll
    for (int nt = 0; nt < 4; nt++) {
        const int cg = colBase + n0 + nt * 8 + tig * 2;
        float2 bv = *(const float2*)(bias + cg);
        #pragma unroll
        for (int mt = 0; mt < 4; mt++) {
            int rg0 = rowBase + m0 + mt * 16 + gid;
            float2 v0 = make_float2(acc[mt][nt][0] + bv.x, acc[mt][nt][1] + bv.y);
            float2 v1 = make_float2(acc[mt][nt][2] + bv.x, acc[mt][nt][3] + bv.y);
            *(float2*)(C + (size_t)rg0 * OUTP + cg) = v0;
            *(float2*)(C + (size_t)(rg0 + 8) * OUTP + cg) = v1;
        }
    }
}

// ---------------------------------------------------------------------------
__global__ __launch_bounds__(256) void stats_kernel(
    const float* __restrict__ y, int rows, float* __restrict__ stats)
{
    int c = threadIdx.x;
    float s = 0.f, q = 0.f;
    for (int r = blockIdx.x; r < rows; r += gridDim.x) {
        float v = y[(size_t)r * OUTP + c];
        s += v;
        q = fmaf(v, v, q);
    }
    atomicAdd(&stats[c], s);
    atomicAdd(&stats[OUTP + c], q);
}

__global__ void finalize_kernel(const float* __restrict__ stats,
                                const float* __restrict__ gamma,
                                const float* __restrict__ beta,
                                float inv_count, float* __restrict__ ab)
{
    int c = threadIdx.x;
    float mean = stats[c] * inv_count;
    float var  = stats[OUTP + c] * inv_count - mean * mean;
    float scale = gamma[c] * rsqrtf(var + 1e-5f);
    ab[c]        = scale;
    ab[OUTP + c] = beta[c] - mean * scale;
}

// ---------------------------------------------------------------------------
// 3-NN (R3 proven scan)
__global__ __launch_bounds__(256) void knn_kernel(
    const float* __restrict__ p1, const float* __restrict__ p2)
{
    __shared__ float4 sp[N2];
    const int b     = blockIdx.x >> 5;
    const int chunk = blockIdx.x & 31;

    const float* P2 = p2 + (size_t)b * N2 * 3;
    for (int i = threadIdx.x; i < N2; i += 256) {
        float x = P2[i * 3 + 0], y = P2[i * 3 + 1], z = P2[i * 3 + 2];
        sp[i] = make_float4(x, y, z, fmaf(x, x, fmaf(y, y, z * z)));
    }
    __syncthreads();

    const int n = chunk * 256 + threadIdx.x;
    const float* P1 = p1 + ((size_t)b * N1 + n) * 3;
    const float px = P1[0], py = P1[1], pz = P1[2];
    const float s1 = fmaf(px, px, fmaf(py, py, pz * pz));

    float d0 = 1e30f, d1 = 1e30f, d2 = 1e30f;
    int   i0 = 0,     i1 = 0,     i2 = 0;

    #pragma unroll 4
    for (int j = 0; j < N2; j++) {
        float4 qq = sp[j];
        float dot = fmaf(px, qq.x, fmaf(py, qq.y, pz * qq.z));
        float d = (s1 + qq.w) - 2.f * dot;
        if (d < d2) {
            if (d < d1) {
                d2 = d1; i2 = i1;
                if (d < d0) { d1 = d0; i1 = i0; d0 = d; i0 = j; }
                else        { d1 = d;  i1 = j; }
            } else { d2 = d; i2 = j; }
        }
    }

    float r0 = 1.f / (d0 + 1e-8f);
    float r1 = 1.f / (d1 + 1e-8f);
    float r2 = 1.f / (d2 + 1e-8f);
    float rs = 1.f / (r0 + r1 + r2);

    size_t o = ((size_t)b * N1 + n) * 3;
    g_idx[o + 0] = b * N2 + i0;
    g_idx[o + 1] = b * N2 + i1;
    g_idx[o + 2] = b * N2 + i2;
    g_w[o + 0] = r0 * rs;
    g_w[o + 1] = r1 * rs;
    g_w[o + 2] = r2 * rs;
}

// ---------------------------------------------------------------------------
__global__ __launch_bounds__(256) void out_kernel(float* __restrict__ out)
{
    const int r = blockIdx.x;
    const int c = threadIdx.x;

    const float a1 = g_ab1[c], s1 = g_ab1[OUTP + c];
    const float a2 = g_ab2[c], s2 = g_ab2[OUTP + c];

    const size_t o3 = (size_t)r * 3;
    const int   j0 = g_idx[o3 + 0], j1 = g_idx[o3 + 1], j2 = g_idx[o3 + 2];
    const float w0 = g_w[o3 + 0],   w1 = g_w[o3 + 1],   w2 = g_w[o3 + 2];

    float v1 = fmaxf(fmaf(g_y1[(size_t)r * OUTP + c], a1, s1), 0.f);
    float h0 = fmaxf(fmaf(g_y2[(size_t)j0 * OUTP + c], a2, s2), 0.f);
    float h1 = fmaxf(fmaf(g_y2[(size_t)j1 * OUTP + c], a2, s2), 0.f);
    float h2 = fmaxf(fmaf(g_y2[(size_t)j2 * OUTP + c], a2, s2), 0.f);

    out[(size_t)r * OUTP + c] = v1 + fmaf(w0, h0, fmaf(w1, h1, w2 * h2));
}

// ---------------------------------------------------------------------------
extern "C" void kernel_launch(void* const* d_in, const int* in_sizes, int n_in,
                              void* d_out, int out_size)
{
    const float* p1     = (const float*)d_in[0];
    const float* x1     = (const float*)d_in[1];
    const float* p2     = (const float*)d_in[2];
    const float* x2     = (const float*)d_in[3];
    const float* W1     = (const float*)d_in[4];
    const float* b1     = (const float*)d_in[5];
    const float* gamma1 = (const float*)d_in[6];
    const float* beta1  = (const float*)d_in[7];
    const float* W2     = (const float*)d_in[8];
    const float* b2     = (const float*)d_in[9];
    const float* gamma2 = (const float*)d_in[10];
    const float* beta2  = (const float*)d_in[11];
    float* out = (float*)d_out;

    float *y1, *y2, *st1, *st2, *ab1, *ab2, *wt1, *wt2;
    cudaGetSymbolAddress((void**)&y1,  g_y1);
    cudaGetSymbolAddress((void**)&y2,  g_y2);
    cudaGetSymbolAddress((void**)&st1, g_stats1);
    cudaGetSymbolAddress((void**)&st2, g_stats2);
    cudaGetSymbolAddress((void**)&ab1, g_ab1);
    cudaGetSymbolAddress((void**)&ab2, g_ab2);
    cudaGetSymbolAddress((void**)&wt1, g_Wt1);
    cudaGetSymbolAddress((void**)&wt2, g_Wt2);

    cudaFuncSetAttribute(gemm_tf32_pipe_kernel<INP>,
                         cudaFuncAttributeMaxDynamicSharedMemorySize, GEMM_SMEM);
    cudaFuncSetAttribute(gemm_tf32_pipe_kernel<OUTP>,
                         cudaFuncAttributeMaxDynamicSharedMemorySize, GEMM_SMEM);

    zero_stats_kernel<<<1, 512>>>();

    // Transpose weights into [N,K]
    transpose_kernel<<<dim3(OUTP / 32, INP / 32), dim3(32, 8)>>>(W2, wt2, INP, OUTP);
    transpose_kernel<<<dim3(OUTP / 32, OUTP / 32), dim3(32, 8)>>>(W1, wt1, OUTP, OUTP);

    // cp.async-pipelined TF32 GEMMs
    gemm_tf32_pipe_kernel<INP><<<dim3(2, M2 / 128), 256, GEMM_SMEM>>>(x2, wt2, b2, y2);
    gemm_tf32_pipe_kernel<OUTP><<<dim3(2, M1 / 128), 256, GEMM_SMEM>>>(x1, wt1, b1, y1);

    stats_kernel<<<512, 256>>>(y2, M2, st2);
    stats_kernel<<<2048, 256>>>(y1, M1, st1);

    finalize_kernel<<<1, 256>>>(st2, gamma2, beta2, 1.f / (float)M2, ab2);
    finalize_kernel<<<1, 256>>>(st1, gamma1, beta1, 1.f / (float)M1, ab1);

    knn_kernel<<<BB * (N1 / 256), 256>>>(p1, p2);

    out_kernel<<<M1, 256>>>(out);
}